// round 8
// baseline (speedup 1.0000x reference)
#include <cuda_runtime.h>
#include <cuda_bf16.h>
#include <cstdint>

// Problem constants (fixed by the dataset): B=1024, T=512, K=64 tags.
#define KTAG 64
#define MAXB 1024
#define MAXT 512
#define NEGV -10000.0f

// Interleaved scratch: g_fm[b][t][j] = (fv, m) pair.
__device__ float g_fm[(size_t)MAXB * MAXT * KTAG * 2];
__device__ float g_scratch[(size_t)MAXB * MAXT];
__device__ float g_scratch_score[MAXB];

// ---- cp.async helpers ----
__device__ __forceinline__ void cp_async16(void* smem_dst, const void* gmem_src) {
    unsigned int d = (unsigned int)__cvta_generic_to_shared(smem_dst);
    asm volatile("cp.async.cg.shared.global [%0], [%1], 16;" :: "r"(d), "l"(gmem_src));
}
#define CP_COMMIT()  asm volatile("cp.async.commit_group;")
#define CP_WAIT(n)   asm volatile("cp.async.wait_group %0;" :: "n"(n))

#define CH 8      // backward: timesteps per staged chunk; buffer holds CH+1 rows
#define PF 4      // forward: emission prefetch ring depth (power of two)

// ============================================================================
// Fused Viterbi, 2 batches per block (64 threads = 2 warps).
// Forward: thread j owns tag j for BOTH batches; loop over max(len0,len1);
//   per-batch updates predicated (uniform). One barrier serves both batches.
// Backward: warp w backtraces batch 2*blk+w by equality match against m.
// ============================================================================
__global__ __launch_bounds__(KTAG) void crf_fused2(
    const float* __restrict__ feats,
    const float* __restrict__ weights,
    const int* __restrict__ lens,
    float* __restrict__ score_out,
    float* __restrict__ path_out,
    int T)
{
    const int blk = blockIdx.x;
    const int b0 = 2 * blk, b1 = 2 * blk + 1;
    const int j = threadIdx.x;          // tag (forward phase)
    const int lane = j & 31;
    const int warp = j >> 5;

    __shared__ __align__(16) float fv_sh[2][2][KTAG];            // [pp][batch][tag]
    __shared__ __align__(16) float w_sh[KTAG * KTAG];            // 16 KB
    __shared__ __align__(16) float buf[2][2][(CH + 1) * 128];    // [warp][pp] 18.4 KB
    __shared__ float path_sh[2][MAXT];                           // 4 KB
    __shared__ float red_v[2][2];
    __shared__ int   red_i[2][2];
    __shared__ int   s_last[2];

    // Stage weights into shared (used by terminal + backward).
    for (int q = j; q < (KTAG * KTAG) / 4; q += KTAG)
        reinterpret_cast<float4*>(w_sh)[q] = reinterpret_cast<const float4*>(weights)[q];

    // Weight row w[j][0..63] in registers (shared across both batches).
    float w[KTAG];
    {
        const float4* wrow = reinterpret_cast<const float4*>(weights + j * KTAG);
        #pragma unroll
        for (int i = 0; i < KTAG / 4; ++i) {
            float4 v = wrow[i];
            w[4 * i + 0] = v.x; w[4 * i + 1] = v.y;
            w[4 * i + 2] = v.z; w[4 * i + 3] = v.w;
        }
    }

    fv_sh[0][0][j] = (j == 0) ? 0.0f : NEGV;
    fv_sh[0][1][j] = (j == 0) ? 0.0f : NEGV;

    const int len0 = lens[b0];
    const int len1 = lens[b1];
    const int lmax = max(len0, len1);

    const size_t base0 = (size_t)b0 * T * KTAG;
    const size_t base1 = (size_t)b1 * T * KTAG;
    float2* __restrict__ fm0 = reinterpret_cast<float2*>(g_fm) + base0;
    float2* __restrict__ fm1 = reinterpret_cast<float2*>(g_fm) + base1;

    // Emission prefetch rings.
    float fr0[PF], fr1[PF];
    #pragma unroll
    for (int k = 0; k < PF; ++k) {
        fr0[k] = (k < len0) ? feats[base0 + (size_t)k * KTAG + j] : 0.0f;
        fr1[k] = (k < len1) ? feats[base1 + (size_t)k * KTAG + j] : 0.0f;
    }

    __syncthreads();

    // ---------------- forward ----------------
    for (int t = 0; t < lmax; ++t) {
        const int rb = t & 1;
        const float feat0 = fr0[t & (PF - 1)];
        const float feat1 = fr1[t & (PF - 1)];

        // batch 0 max chains
        float a0 = -3.0e38f, a1 = -3.0e38f, a2 = -3.0e38f, a3 = -3.0e38f;
        float c0 = -3.0e38f, c1 = -3.0e38f, c2 = -3.0e38f, c3 = -3.0e38f;
        const float4* f0v = reinterpret_cast<const float4*>(fv_sh[rb][0]);
        const float4* f1v = reinterpret_cast<const float4*>(fv_sh[rb][1]);
        #pragma unroll
        for (int i = 0; i < 16; i += 2) {
            float4 p0 = f0v[i];
            float4 p1 = f0v[i + 1];
            float4 q0 = f1v[i];
            float4 q1 = f1v[i + 1];
            a0 = fmaxf(a0, p0.x + w[4 * i + 0]);
            a1 = fmaxf(a1, p0.y + w[4 * i + 1]);
            a2 = fmaxf(a2, p0.z + w[4 * i + 2]);
            a3 = fmaxf(a3, p0.w + w[4 * i + 3]);
            c0 = fmaxf(c0, q0.x + w[4 * i + 0]);
            c1 = fmaxf(c1, q0.y + w[4 * i + 1]);
            c2 = fmaxf(c2, q0.z + w[4 * i + 2]);
            c3 = fmaxf(c3, q0.w + w[4 * i + 3]);
            a0 = fmaxf(a0, p1.x + w[4 * i + 4]);
            a1 = fmaxf(a1, p1.y + w[4 * i + 5]);
            a2 = fmaxf(a2, p1.z + w[4 * i + 6]);
            a3 = fmaxf(a3, p1.w + w[4 * i + 7]);
            c0 = fmaxf(c0, q1.x + w[4 * i + 4]);
            c1 = fmaxf(c1, q1.y + w[4 * i + 5]);
            c2 = fmaxf(c2, q1.z + w[4 * i + 6]);
            c3 = fmaxf(c3, q1.w + w[4 * i + 7]);
        }
        const float m0 = fmaxf(fmaxf(a0, a1), fmaxf(a2, a3));
        const float m1 = fmaxf(fmaxf(c0, c1), fmaxf(c2, c3));

        if (t < len0) {
            const float nf = m0 + feat0;
            fv_sh[rb ^ 1][0][j] = nf;
            fm0[(size_t)t * KTAG + j] = make_float2(nf, m0);
            if (t + PF < len0)
                fr0[t & (PF - 1)] = feats[base0 + (size_t)(t + PF) * KTAG + j];
        }
        if (t < len1) {
            const float nf = m1 + feat1;
            fv_sh[rb ^ 1][1][j] = nf;
            fm1[(size_t)t * KTAG + j] = make_float2(nf, m1);
            if (t + PF < len1)
                fr1[t & (PF - 1)] = feats[base1 + (size_t)(t + PF) * KTAG + j];
        }
        __syncthreads();
    }

    // Terminal per batch: fv + weights[END=1][prev]; first-index argmax.
    #pragma unroll
    for (int k = 0; k < 2; ++k) {
        const int lk = k == 0 ? len0 : len1;
        float v = fv_sh[lk & 1][k][j] + w_sh[KTAG + j];
        int idx = j;
        #pragma unroll
        for (int off = 16; off; off >>= 1) {
            float ov = __shfl_xor_sync(0xffffffffu, v, off);
            int   oi = __shfl_xor_sync(0xffffffffu, idx, off);
            if (ov > v || (ov == v && oi < idx)) { v = ov; idx = oi; }
        }
        if (lane == 0) { red_v[k][warp] = v; red_i[k][warp] = idx; }
    }
    __syncthreads();
    if (j < 2) {
        const int bq = j == 0 ? b0 : b1;
        float v0 = red_v[j][0], v1 = red_v[j][1];
        if (v1 > v0) { score_out[bq] = v1; s_last[j] = red_i[j][1]; }
        else         { score_out[bq] = v0; s_last[j] = red_i[j][0]; }
    }
    __syncthreads();

    // ---------------- backward: warp w -> batch 2*blk + w ----------------
    const int bw   = 2 * blk + warp;
    const int len  = warp == 0 ? len0 : len1;
    int tag        = s_last[warp];
    const float* __restrict__ fm = g_fm + (((size_t)bw * T * KTAG) << 1);
    float* pathw = path_sh[warp];

    for (int q = len + lane; q < T; q += 32)
        pathw[q] = (float)tag;

    auto stage = [&](int lo, int bi) {
        const int r0 = lo - 1;
        #pragma unroll
        for (int s = 0; s < CH + 1; ++s) {
            const int r = r0 + s;
            if (r >= 0 && r < len)
                cp_async16(&buf[warp][bi][s * 128 + lane * 4],
                           fm + ((size_t)r * 128 + lane * 4));
        }
        CP_COMMIT();
    };

    const int hi0 = ((len + CH - 1) / CH) * CH;
    int bi = 0;
    stage(hi0 - CH, 0);

    for (int hi = hi0; hi > 0; hi -= CH) {
        const int lo = hi - CH;
        if (lo > 0) { stage(lo - CH, bi ^ 1); CP_WAIT(1); }
        else        { CP_WAIT(0); }
        __syncwarp();

        const float* bufc = buf[warp][bi];
        for (int t = hi - 1; t >= lo; --t) {
            if (lane == 0 && t < len) pathw[t] = (float)tag;
            if (t >= 1 && t < len) {
                const float target = bufc[(t - lo + 1) * 128 + 2 * tag + 1]; // m[t][tag]
                const float* rowb = bufc + (t - lo) * 128;                   // fv[t-1]
                const float* wr = w_sh + tag * KTAG;
                float2 f0 = *reinterpret_cast<const float2*>(rowb + 2 * lane);
                float2 f1 = *reinterpret_cast<const float2*>(rowb + 64 + 2 * lane);
                const bool p0 = (f0.x + wr[lane])      == target;
                const bool p1 = (f1.x + wr[lane + 32]) == target;
                const unsigned e0 = __ballot_sync(0xffffffffu, p0);
                const unsigned e1 = __ballot_sync(0xffffffffu, p1);
                tag = e0 ? (__ffs(e0) - 1) : (__ffs(e1) + 31);
            }
        }
        bi ^= 1;
        __syncwarp();
    }

    for (int q = lane; q < T; q += 32)
        path_out[(size_t)bw * T + q] = pathw[q];
}

extern "C" void kernel_launch(void* const* d_in, const int* in_sizes, int n_in,
                              void* d_out, int out_size) {
    const float* feats   = (const float*)d_in[0];
    const float* weights = (const float*)d_in[1];
    const int*   lens    = (const int*)d_in[2];

    const int B = in_sizes[2];
    const int K = KTAG;
    const int T = in_sizes[0] / (B * K);

    float* out = (float*)d_out;
    float* score_ptr;
    float* path_ptr;

    if (out_size == B * (T + 1)) {          // [score B | paths B*T]
        score_ptr = out;
        path_ptr  = out + B;
    } else if (out_size == B) {             // score only
        score_ptr = out;
        void* p; cudaGetSymbolAddress(&p, g_scratch);
        path_ptr = (float*)p;
    } else {                                // paths only
        path_ptr = out;
        void* p; cudaGetSymbolAddress(&p, g_scratch_score);
        score_ptr = (float*)p;
    }

    crf_fused2<<<B / 2, KTAG>>>(feats, weights, lens, score_ptr, path_ptr, T);
}

// round 9
// speedup vs baseline: 2.4820x; 2.4820x over previous
#include <cuda_runtime.h>
#include <cuda_bf16.h>
#include <cstdint>

// Problem constants (fixed by the dataset): B=1024, T=512, K=64 tags.
#define KTAG 64
#define MAXB 1024
#define MAXT 512
#define NEGV -10000.0f

// Interleaved scratch: g_fm[b][t][j] = (fv, m) pair.
//   fv = viterbi value AFTER step t (max + emission)
//   m  = max_prev(fv_prev + w[j][prev]) BEFORE emission (backtrace target)
__device__ float g_fm[(size_t)MAXB * MAXT * KTAG * 2];
__device__ float g_scratch[(size_t)MAXB * MAXT];
__device__ float g_scratch_score[MAXB];

// ---- cp.async helpers ----
__device__ __forceinline__ void cp_async16(void* smem_dst, const void* gmem_src) {
    unsigned int d = (unsigned int)__cvta_generic_to_shared(smem_dst);
    asm volatile("cp.async.cg.shared.global [%0], [%1], 16;" :: "r"(d), "l"(gmem_src));
}
#define CP_COMMIT()  asm volatile("cp.async.commit_group;")
#define CP_WAIT(n)   asm volatile("cp.async.wait_group %0;" :: "n"(n))

#define CH 8      // backward: timesteps per staged chunk; buffer holds CH+1 rows

// ============================================================================
// Fused Viterbi: one block (64 threads = 2 warps) per batch.
// Phase 1 (both warps): forward recurrence, thread j owns next-tag j.
//   new_fv[j] = max_prev(fv[prev] + w[j][prev]) + feat[t][j]
//   Time loop hand-unrolled x4 so the emission prefetch ring is four NAMED
//   SCALARS (f0..f3) — no runtime-indexed register array, no local memory.
// Phase 2 (warp 0 only): backtrace by equality match against stored m.
// ============================================================================
__global__ __launch_bounds__(KTAG) void crf_fused(
    const float* __restrict__ feats,
    const float* __restrict__ weights,
    const int* __restrict__ lens,
    float* __restrict__ score_out,
    float* __restrict__ path_out,
    int T)
{
    const int b = blockIdx.x;
    const int j = threadIdx.x;          // next tag (forward phase)
    const int lane = j & 31;
    const int warp = j >> 5;

    __shared__ __align__(16) float fv_sh[2][KTAG];
    __shared__ __align__(16) float w_sh[KTAG * KTAG];        // 16 KB (backward)
    __shared__ __align__(16) float buf[2][(CH + 1) * 128];   // 9.2 KB (backward)
    __shared__ float path_sh[MAXT];                          // 2 KB
    __shared__ float red_v[2];
    __shared__ int   red_i[2];
    __shared__ int   s_last;

    // Stage weights into shared for backward (also warms L1 for reg loads).
    for (int q = j; q < (KTAG * KTAG) / 4; q += KTAG)
        reinterpret_cast<float4*>(w_sh)[q] = reinterpret_cast<const float4*>(weights)[q];

    // Weight row w[j][0..63] in registers (constant-indexed everywhere).
    float w[KTAG];
    {
        const float4* wrow = reinterpret_cast<const float4*>(weights + j * KTAG);
        #pragma unroll
        for (int i = 0; i < KTAG / 4; ++i) {
            float4 v = wrow[i];
            w[4 * i + 0] = v.x; w[4 * i + 1] = v.y;
            w[4 * i + 2] = v.z; w[4 * i + 3] = v.w;
        }
    }

    fv_sh[0][j] = (j == 0) ? 0.0f : NEGV;

    const int len = lens[b];            // 1..T
    const size_t base = (size_t)b * T * KTAG;
    const float* __restrict__ fcol = feats + base + j;      // column for tag j
    float2* __restrict__ fm_out = reinterpret_cast<float2*>(g_fm) + base + j;

    float curv = (j == 0) ? 0.0f : NEGV;

    // Emission prefetch: four named scalars (registers).
    float f0 = fcol[0];
    float f1 = (1 < len) ? fcol[1 * KTAG] : 0.0f;
    float f2 = (2 < len) ? fcol[2 * KTAG] : 0.0f;
    float f3 = (3 < len) ? fcol[3 * KTAG] : 0.0f;

    __syncthreads();

    // ---------------- forward (unrolled x4, uniform guards) ----------------
    #define FWD_STEP(T_IDX, FREG, PREFETCH_IDX)                                   \
        if ((T_IDX) < len) {                                                      \
            const int rb = (T_IDX) & 1;                                           \
            float a0 = -3.0e38f, a1 = -3.0e38f, a2 = -3.0e38f, a3 = -3.0e38f;     \
            float a4 = -3.0e38f, a5 = -3.0e38f, a6 = -3.0e38f, a7 = -3.0e38f;     \
            const float4* fvv = reinterpret_cast<const float4*>(fv_sh[rb]);       \
            _Pragma("unroll")                                                     \
            for (int i = 0; i < 16; i += 2) {                                     \
                float4 p0 = fvv[i];                                               \
                float4 p1 = fvv[i + 1];                                           \
                a0 = fmaxf(a0, p0.x + w[4 * i + 0]);                              \
                a1 = fmaxf(a1, p0.y + w[4 * i + 1]);                              \
                a2 = fmaxf(a2, p0.z + w[4 * i + 2]);                              \
                a3 = fmaxf(a3, p0.w + w[4 * i + 3]);                              \
                a4 = fmaxf(a4, p1.x + w[4 * i + 4]);                              \
                a5 = fmaxf(a5, p1.y + w[4 * i + 5]);                              \
                a6 = fmaxf(a6, p1.z + w[4 * i + 6]);                              \
                a7 = fmaxf(a7, p1.w + w[4 * i + 7]);                              \
            }                                                                     \
            a0 = fmaxf(a0, a1); a2 = fmaxf(a2, a3);                               \
            a4 = fmaxf(a4, a5); a6 = fmaxf(a6, a7);                               \
            a0 = fmaxf(a0, a2); a4 = fmaxf(a4, a6);                               \
            const float m = fmaxf(a0, a4);                                        \
            const float nf = m + (FREG);                                          \
            curv = nf;                                                            \
            fv_sh[rb ^ 1][j] = nf;                                                \
            fm_out[(size_t)(T_IDX) * KTAG] = make_float2(nf, m);                  \
            if ((PREFETCH_IDX) < len)                                             \
                (FREG) = fcol[(size_t)(PREFETCH_IDX) * KTAG];                     \
            __syncthreads();                                                      \
        }

    for (int t0 = 0; t0 < len; t0 += 4) {
        FWD_STEP(t0 + 0, f0, t0 + 4)
        FWD_STEP(t0 + 1, f1, t0 + 5)
        FWD_STEP(t0 + 2, f2, t0 + 6)
        FWD_STEP(t0 + 3, f3, t0 + 7)
    }
    #undef FWD_STEP

    // Terminal: fv + weights[END=1][prev]; argmax, first-index tie-break.
    {
        float v = curv + w_sh[KTAG + j];
        int idx = j;
        #pragma unroll
        for (int off = 16; off; off >>= 1) {
            float ov = __shfl_xor_sync(0xffffffffu, v, off);
            int   oi = __shfl_xor_sync(0xffffffffu, idx, off);
            if (ov > v || (ov == v && oi < idx)) { v = ov; idx = oi; }
        }
        if (lane == 0) { red_v[warp] = v; red_i[warp] = idx; }
    }
    __syncthreads();
    if (j == 0) {
        float v0 = red_v[0], v1 = red_v[1];
        if (v1 > v0) { score_out[b] = v1; s_last = red_i[1]; }
        else         { score_out[b] = v0; s_last = red_i[0]; }
    }
    __syncthreads();

    // ---------------- backward (warp 0 only) ----------------
    if (warp != 0) return;

    int tag = s_last;
    const float* __restrict__ fm = g_fm + (base << 1);   // floats

    // padding region: path[t] = best_last for t >= len
    for (int q = len + lane; q < T; q += 32)
        path_sh[q] = (float)tag;

    // Stage rows r = lo-1 .. lo-1+CH (interleaved fv,m; 128 floats = 32x16B each).
    auto stage = [&](int lo, int bi) {
        const int r0 = lo - 1;
        #pragma unroll
        for (int s = 0; s < CH + 1; ++s) {
            const int r = r0 + s;
            if (r >= 0 && r < len)
                cp_async16(&buf[bi][s * 128 + lane * 4],
                           fm + ((size_t)r * 128 + lane * 4));
        }
        CP_COMMIT();
    };

    const int hi0 = ((len + CH - 1) / CH) * CH;   // first chunk boundary >= len
    int bi = 0;
    stage(hi0 - CH, 0);

    for (int hi = hi0; hi > 0; hi -= CH) {
        const int lo = hi - CH;
        if (lo > 0) { stage(lo - CH, bi ^ 1); CP_WAIT(1); }
        else        { CP_WAIT(0); }
        __syncwarp();

        const float* bufc = buf[bi];
        for (int t = hi - 1; t >= lo; --t) {
            if (lane == 0 && t < len) path_sh[t] = (float)tag;
            if (t >= 1 && t < len) {
                const float target = bufc[(t - lo + 1) * 128 + 2 * tag + 1]; // m[t][tag]
                const float* rowb = bufc + (t - lo) * 128;                   // fv[t-1]
                const float* wr = w_sh + tag * KTAG;
                float2 q0 = *reinterpret_cast<const float2*>(rowb + 2 * lane);
                float2 q1 = *reinterpret_cast<const float2*>(rowb + 64 + 2 * lane);
                const bool p0 = (q0.x + wr[lane])      == target;
                const bool p1 = (q1.x + wr[lane + 32]) == target;
                const unsigned e0 = __ballot_sync(0xffffffffu, p0);
                const unsigned e1 = __ballot_sync(0xffffffffu, p1);
                tag = e0 ? (__ffs(e0) - 1) : (__ffs(e1) + 31);
            }
        }
        bi ^= 1;
        __syncwarp();   // all lanes done reading before this buffer is re-staged
    }

    for (int q = lane; q < T; q += 32)
        path_out[(size_t)b * T + q] = path_sh[q];
}

extern "C" void kernel_launch(void* const* d_in, const int* in_sizes, int n_in,
                              void* d_out, int out_size) {
    const float* feats   = (const float*)d_in[0];
    const float* weights = (const float*)d_in[1];
    const int*   lens    = (const int*)d_in[2];

    const int B = in_sizes[2];
    const int K = KTAG;
    const int T = in_sizes[0] / (B * K);

    float* out = (float*)d_out;
    float* score_ptr;
    float* path_ptr;

    if (out_size == B * (T + 1)) {          // [score B | paths B*T]
        score_ptr = out;
        path_ptr  = out + B;
    } else if (out_size == B) {             // score only
        score_ptr = out;
        void* p; cudaGetSymbolAddress(&p, g_scratch);
        path_ptr = (float*)p;
    } else {                                // paths only
        path_ptr = out;
        void* p; cudaGetSymbolAddress(&p, g_scratch_score);
        score_ptr = (float*)p;
    }

    crf_fused<<<B, KTAG>>>(feats, weights, lens, score_ptr, path_ptr, T);
}